// round 2
// baseline (speedup 1.0000x reference)
#include <cuda_runtime.h>
#include <math.h>

// ContractiveMessageBlock fused kernel — Round 0 fp32 baseline.
// Structure: [zero accumulators] -> [fused edge kernel: GEMM1+silu+GEMM2(3 chunks)
//            + RBF filter + split + atomic scatter] -> [finalize: mean + transpose]

#define E_TOT   200000
#define FEAT    128
#define TM      64           // edges per block
#define NB      2000         // num CG beads
#define NRBF    20
#define PI_F    3.14159265358979323846f
#define PI_OVER_CUT 0.62831853071795864769f  // pi/5

// SMEM layout (floats):
//   sS   [64][132]  s tile (reused as split0 stash after GEMM1)
//   sH   [64][132]  silu hidden
//   sW   [128][128] W1, then W2 chunks
//   sRbf [64][20]
//   sUnit[64][3]
//   sEnv [64]
//   sBin [64] (int)
#define SM_FLOATS (64*132 + 64*132 + 128*128 + 64*20 + 64*3 + 64 + 64)
#define SMEM_BYTES (SM_FLOATS * 4)

__device__ float g_acc_s[NB * FEAT];      // [bin][f]
__device__ float g_acc_v[NB * 3 * FEAT];  // [bin][x][f]
__device__ float g_cnt[NB];

__global__ void cmb_zero() {
    int i = blockIdx.x * 256 + threadIdx.x;
    if (i < NB * FEAT)     g_acc_s[i] = 0.0f;
    if (i < NB * 3 * FEAT) g_acc_v[i] = 0.0f;
    if (i < NB)            g_cnt[i]   = 0.0f;
}

__global__ void __launch_bounds__(256, 1)
cmb_main(const float* __restrict__ s_i, const float* __restrict__ v_i,
         const float* __restrict__ r_iI, const float* __restrict__ W1,
         const float* __restrict__ b1, const float* __restrict__ W2,
         const float* __restrict__ b2, const float* __restrict__ Wr,
         const float* __restrict__ br, const int* __restrict__ mapping)
{
    extern __shared__ float sm[];
    float* sS    = sm;                     // 64*132
    float* sH    = sS + 64 * 132;          // 64*132
    float* sW    = sH + 64 * 132;          // 128*128
    float* sRbf  = sW + 128 * 128;         // 64*20
    float* sUnit = sRbf + 64 * 20;         // 64*3
    float* sEnv  = sUnit + 64 * 3;         // 64
    int*   sBin  = (int*)(sEnv + 64);      // 64

    const int tid = threadIdx.x;
    const long e0 = (long)blockIdx.x * TM;

    // ---- load s tile [64][128] -> sS (padded stride 132) ----
    {
        const float4* g = (const float4*)(s_i + e0 * FEAT);
        for (int i = tid; i < 64 * 32; i += 256) {
            int e = i >> 5, c = i & 31;
            *(float4*)&sS[e * 132 + c * 4] = g[i];
        }
    }
    // ---- load W1 [128][128] -> sW ----
    {
        const float4* g = (const float4*)W1;
        for (int i = tid; i < 128 * 32; i += 256)
            *(float4*)&sW[i * 4] = g[i];
    }
    // ---- per-edge preprocess: dist/unit/env/rbf/bin/count ----
    if (tid < TM) {
        long eg = e0 + tid;
        float r0 = r_iI[eg * 3 + 0], r1 = r_iI[eg * 3 + 1], r2 = r_iI[eg * 3 + 2];
        float d  = sqrtf(r0 * r0 + r1 * r1 + r2 * r2 + 3e-8f);
        float id = 1.0f / d;
        sUnit[tid * 3 + 0] = r0 * id;
        sUnit[tid * 3 + 1] = r1 * id;
        sUnit[tid * 3 + 2] = r2 * id;
        sEnv[tid] = (d < 5.0f) ? 0.5f * (cosf(PI_OVER_CUT * d) + 1.0f) : 0.0f;
        float ang = PI_OVER_CUT * d;
        #pragma unroll
        for (int n = 0; n < NRBF; n++)
            sRbf[tid * NRBF + n] = sinf((float)(n + 1) * ang) * id;
        int b = mapping[eg];
        sBin[tid] = b;
        atomicAdd(&g_cnt[b], 1.0f);
    }
    __syncthreads();

    const int tx = tid & 31, ty = tid >> 5;
    const int j0 = tx * 4;      // 4 contiguous output cols per thread
    const int eb = ty * 8;      // 8 edges per thread

    // ---- GEMM1: C = s @ W1, 8x4 register tile per thread ----
    float acc[8][4];
    #pragma unroll
    for (int r = 0; r < 8; r++)
        acc[r][0] = acc[r][1] = acc[r][2] = acc[r][3] = 0.0f;

    #pragma unroll 4
    for (int k = 0; k < FEAT; k++) {
        float4 b4 = *(float4*)&sW[k * 128 + j0];
        #pragma unroll
        for (int r = 0; r < 8; r++) {
            float a = sS[(eb + r) * 132 + k];
            acc[r][0] = fmaf(a, b4.x, acc[r][0]);
            acc[r][1] = fmaf(a, b4.y, acc[r][1]);
            acc[r][2] = fmaf(a, b4.z, acc[r][2]);
            acc[r][3] = fmaf(a, b4.w, acc[r][3]);
        }
    }
    // ---- bias + silu -> sH ----
    {
        float4 bb = *(const float4*)&b1[j0];
        #pragma unroll
        for (int r = 0; r < 8; r++) {
            float4 h;
            float x0 = acc[r][0] + bb.x; h.x = x0 / (1.0f + __expf(-x0));
            float x1 = acc[r][1] + bb.y; h.y = x1 / (1.0f + __expf(-x1));
            float x2 = acc[r][2] + bb.z; h.z = x2 / (1.0f + __expf(-x2));
            float x3 = acc[r][3] + bb.w; h.w = x3 / (1.0f + __expf(-x3));
            *(float4*)&sH[(eb + r) * 132 + j0] = h;
        }
    }

    // ---- 3 chunks of GEMM2 (N=128 each) + fused epilogue ----
    for (int c = 0; c < 3; c++) {
        __syncthreads();   // protect sW before overwrite
        for (int i = tid; i < 128 * 32; i += 256) {
            int k = i >> 5, jj = (i & 31) * 4;
            *(float4*)&sW[k * 128 + jj] = *(const float4*)&W2[k * 384 + c * 128 + jj];
        }
        __syncthreads();

        float a2[8][4];
        #pragma unroll
        for (int r = 0; r < 8; r++)
            a2[r][0] = a2[r][1] = a2[r][2] = a2[r][3] = 0.0f;

        #pragma unroll 4
        for (int k = 0; k < FEAT; k++) {
            float4 b4 = *(float4*)&sW[k * 128 + j0];
            #pragma unroll
            for (int r = 0; r < 8; r++) {
                float a = sH[(eb + r) * 132 + k];
                a2[r][0] = fmaf(a, b4.x, a2[r][0]);
                a2[r][1] = fmaf(a, b4.y, a2[r][1]);
                a2[r][2] = fmaf(a, b4.z, a2[r][2]);
                a2[r][3] = fmaf(a, b4.w, a2[r][3]);
            }
        }

        // w_s = (rbf @ Wr + br) * env, per thread for its 8 edges x 4 cols
        float ws[8][4];
        {
            float4 brv = *(const float4*)&br[c * 128 + j0];
            #pragma unroll
            for (int r = 0; r < 8; r++) {
                ws[r][0] = brv.x; ws[r][1] = brv.y; ws[r][2] = brv.z; ws[r][3] = brv.w;
            }
            #pragma unroll
            for (int n = 0; n < NRBF; n++) {
                float4 w4 = *(const float4*)&Wr[n * 384 + c * 128 + j0];
                #pragma unroll
                for (int r = 0; r < 8; r++) {
                    float rb = sRbf[(eb + r) * NRBF + n];
                    ws[r][0] = fmaf(rb, w4.x, ws[r][0]);
                    ws[r][1] = fmaf(rb, w4.y, ws[r][1]);
                    ws[r][2] = fmaf(rb, w4.z, ws[r][2]);
                    ws[r][3] = fmaf(rb, w4.w, ws[r][3]);
                }
            }
        }

        float4 b2v = *(const float4*)&b2[c * 128 + j0];
        #pragma unroll
        for (int r = 0; r < 8; r++) {
            int e = eb + r;
            float envv = sEnv[e];
            float i0 = (a2[r][0] + b2v.x) * (ws[r][0] * envv);
            float i1 = (a2[r][1] + b2v.y) * (ws[r][1] * envv);
            float i2 = (a2[r][2] + b2v.z) * (ws[r][2] * envv);
            float i3 = (a2[r][3] + b2v.w) * (ws[r][3] * envv);

            if (c == 0) {
                // stash split_0 in freed s-tile smem (same thread reads it at c==2)
                sS[e * 132 + j0 + 0] = i0;
                sS[e * 132 + j0 + 1] = i1;
                sS[e * 132 + j0 + 2] = i2;
                sS[e * 132 + j0 + 3] = i3;
            } else if (c == 1) {
                // delta_s scatter
                int bin = sBin[e];
                float* p = &g_acc_s[bin * FEAT + j0];
                atomicAdd(p + 0, i0);
                atomicAdd(p + 1, i1);
                atomicAdd(p + 2, i2);
                atomicAdd(p + 3, i3);
            } else {
                // delta_v = split2 * unit + split0 * v_i, scatter into [bin][x][f]
                int bin = sBin[e];
                long eg = e0 + e;
                float s00 = sS[e * 132 + j0 + 0];
                float s01 = sS[e * 132 + j0 + 1];
                float s02 = sS[e * 132 + j0 + 2];
                float s03 = sS[e * 132 + j0 + 3];
                const float* vg = v_i + ((long)eg * FEAT + j0) * 3;
                #pragma unroll
                for (int x = 0; x < 3; x++) {
                    float u = sUnit[e * 3 + x];
                    float* p = &g_acc_v[bin * 3 * FEAT + x * FEAT + j0];
                    atomicAdd(p + 0, fmaf(i0, u, s00 * vg[0 * 3 + x]));
                    atomicAdd(p + 1, fmaf(i1, u, s01 * vg[1 * 3 + x]));
                    atomicAdd(p + 2, fmaf(i2, u, s02 * vg[2 * 3 + x]));
                    atomicAdd(p + 3, fmaf(i3, u, s03 * vg[3 * 3 + x]));
                }
            }
        }
    }
}

__global__ void cmb_final(float* __restrict__ out) {
    int bin = blockIdx.x;
    int f   = threadIdx.x;
    float ic = 1.0f / fmaxf(g_cnt[bin], 1.0f);
    // delta_s_I : out[0 .. 2000*128)
    out[bin * FEAT + f] = g_acc_s[bin * FEAT + f] * ic;
    // delta_v_I : out[256000 + bin*384 + f*3 + x]  (transpose from [bin][x][f])
    #pragma unroll
    for (int x = 0; x < 3; x++)
        out[NB * FEAT + bin * 384 + f * 3 + x] =
            g_acc_v[bin * 3 * FEAT + x * FEAT + f] * ic;
}

extern "C" void kernel_launch(void* const* d_in, const int* in_sizes, int n_in,
                              void* d_out, int out_size)
{
    const float* s_i     = (const float*)d_in[0];
    const float* v_i     = (const float*)d_in[1];
    const float* r_iI    = (const float*)d_in[2];
    const float* W1      = (const float*)d_in[3];
    const float* b1      = (const float*)d_in[4];
    const float* W2      = (const float*)d_in[5];
    const float* b2      = (const float*)d_in[6];
    const float* Wr      = (const float*)d_in[7];
    const float* br      = (const float*)d_in[8];
    const int*   mapping = (const int*)d_in[9];
    float* out = (float*)d_out;
    (void)in_sizes; (void)n_in; (void)out_size;

    cudaFuncSetAttribute((const void*)cmb_main,
                         cudaFuncAttributeMaxDynamicSharedMemorySize, SMEM_BYTES);

    cmb_zero<<<(NB * 3 * FEAT + 255) / 256, 256>>>();
    cmb_main<<<E_TOT / TM, 256, SMEM_BYTES>>>(s_i, v_i, r_iI, W1, b1, W2, b2,
                                              Wr, br, mapping);
    cmb_final<<<NB, FEAT>>>(out);
}

// round 3
// speedup vs baseline: 1.2373x; 1.2373x over previous
#include <cuda_runtime.h>
#include <math.h>

// ContractiveMessageBlock — Round 2: packed f32x2 GEMMs + red.v4 scatter.

#define E_TOT   200000
#define FEAT    128
#define TM      64
#define NB      2000
#define NRBF    20
#define PI_OVER_CUT 0.62831853071795864769f  // pi/5

typedef unsigned long long u64;

__device__ __forceinline__ u64 fma2(u64 a, u64 b, u64 c) {
    u64 d; asm("fma.rn.f32x2 %0, %1, %2, %3;" : "=l"(d) : "l"(a), "l"(b), "l"(c)); return d;
}
__device__ __forceinline__ u64 mul2(u64 a, u64 b) {
    u64 d; asm("mul.rn.f32x2 %0, %1, %2;" : "=l"(d) : "l"(a), "l"(b)); return d;
}
__device__ __forceinline__ u64 add2(u64 a, u64 b) {
    u64 d; asm("add.rn.f32x2 %0, %1, %2;" : "=l"(d) : "l"(a), "l"(b)); return d;
}
__device__ __forceinline__ u64 dup2(float x) {
    u64 d; asm("mov.b64 %0, {%1, %1};" : "=l"(d) : "f"(x)); return d;
}
__device__ __forceinline__ void unpack2(u64 a, float& lo, float& hi) {
    asm("mov.b64 {%0, %1}, %2;" : "=f"(lo), "=f"(hi) : "l"(a));
}
__device__ __forceinline__ void red_add_v4(float* p, float a, float b, float c, float d) {
    asm volatile("red.global.add.v4.f32 [%0], {%1, %2, %3, %4};"
                 :: "l"(p), "f"(a), "f"(b), "f"(c), "f"(d) : "memory");
}

// SMEM layout (floats)
#define S_STRIDE  132
#define T_STRIDE  68      // transposed tiles: 68*4B = 272B, 16B-aligned rows
#define OFF_SS    0                          // 64*132  = 8448   (staging)
#define OFF_SST   (OFF_SS  + 64*S_STRIDE)    // 128*68  = 8704   (s transposed)
#define OFF_SHT   (OFF_SST + 128*T_STRIDE)   // 128*68  = 8704   (hidden transposed)
#define OFF_SW    (OFF_SHT + 128*T_STRIDE)   // 128*128 = 16384
#define OFF_RBFT  (OFF_SW  + 128*128)        // 20*64   = 1280   (rbf transposed)
#define OFF_UNITT (OFF_RBFT + NRBF*64)       // 3*64    = 192
#define OFF_ENV   (OFF_UNITT + 3*64)         // 64
#define OFF_BIN   (OFF_ENV + 64)             // 64 (int)
#define SM_FLOATS (OFF_BIN + 64)
#define SMEM_BYTES (SM_FLOATS * 4)

__device__ __align__(16) float g_acc_s[NB * FEAT];      // [bin][f]
__device__ __align__(16) float g_acc_v[NB * 3 * FEAT];  // [bin][x][f]
__device__ float g_cnt[NB];

__global__ void cmb_zero() {
    int i = blockIdx.x * 256 + threadIdx.x;
    if (i < NB * FEAT)     g_acc_s[i] = 0.0f;
    if (i < NB * 3 * FEAT) g_acc_v[i] = 0.0f;
    if (i < NB)            g_cnt[i]   = 0.0f;
}

__global__ void __launch_bounds__(256, 1)
cmb_main(const float* __restrict__ s_i, const float* __restrict__ v_i,
         const float* __restrict__ r_iI, const float* __restrict__ W1,
         const float* __restrict__ b1, const float* __restrict__ W2,
         const float* __restrict__ b2, const float* __restrict__ Wr,
         const float* __restrict__ br, const int* __restrict__ mapping)
{
    extern __shared__ float sm[];
    float* sS     = sm + OFF_SS;
    float* sST    = sm + OFF_SST;
    float* sHT    = sm + OFF_SHT;
    float* sW     = sm + OFF_SW;
    float* sRbfT  = sm + OFF_RBFT;
    float* sUnitT = sm + OFF_UNITT;
    float* sEnv   = sm + OFF_ENV;
    int*   sBin   = (int*)(sm + OFF_BIN);

    const int tid = threadIdx.x;
    const long e0 = (long)blockIdx.x * TM;

    // ---- load s tile [64][128] coalesced -> sS staging ----
    {
        const float4* g = (const float4*)(s_i + e0 * FEAT);
        for (int i = tid; i < 64 * 32; i += 256) {
            int e = i >> 5, c = i & 31;
            *(float4*)&sS[e * S_STRIDE + c * 4] = g[i];
        }
    }
    // ---- load W1 ----
    {
        const float4* g = (const float4*)W1;
        for (int i = tid; i < 128 * 32; i += 256)
            *(float4*)&sW[i * 4] = g[i];
    }
    // ---- per-edge preprocess ----
    if (tid < TM) {
        long eg = e0 + tid;
        float r0 = r_iI[eg * 3 + 0], r1 = r_iI[eg * 3 + 1], r2 = r_iI[eg * 3 + 2];
        float d  = sqrtf(r0 * r0 + r1 * r1 + r2 * r2 + 3e-8f);
        float id = 1.0f / d;
        sUnitT[0 * 64 + tid] = r0 * id;
        sUnitT[1 * 64 + tid] = r1 * id;
        sUnitT[2 * 64 + tid] = r2 * id;
        sEnv[tid] = (d < 5.0f) ? 0.5f * (cosf(PI_OVER_CUT * d) + 1.0f) : 0.0f;
        float ang = PI_OVER_CUT * d;
        #pragma unroll
        for (int n = 0; n < NRBF; n++)
            sRbfT[n * 64 + tid] = sinf((float)(n + 1) * ang) * id;
        int b = mapping[eg];
        sBin[tid] = b;
        atomicAdd(&g_cnt[b], 1.0f);
    }
    __syncthreads();

    // ---- transpose s tile: sST[k][e] = sS[e][k] ----
    for (int i = tid; i < 64 * 128; i += 256) {
        int e = i & 63, k = i >> 6;
        sST[k * T_STRIDE + e] = sS[e * S_STRIDE + k];
    }
    __syncthreads();

    const int tx = tid & 31, ty = tid >> 5;
    const int j0 = tx * 4;
    const int eb = ty * 8;

    // ---- GEMM1: packed over edge pairs. acc2[rp][col], rp = edge pair ----
    u64 acc2[4][4];
    #pragma unroll
    for (int rp = 0; rp < 4; rp++)
        acc2[rp][0] = acc2[rp][1] = acc2[rp][2] = acc2[rp][3] = 0ULL;

    #pragma unroll 8
    for (int k = 0; k < FEAT; k++) {
        float4 b4 = *(float4*)&sW[k * 128 + j0];
        u64 bd[4] = { dup2(b4.x), dup2(b4.y), dup2(b4.z), dup2(b4.w) };
        ulonglong2 aA = *(ulonglong2*)&sST[k * T_STRIDE + eb];
        ulonglong2 aB = *(ulonglong2*)&sST[k * T_STRIDE + eb + 4];
        u64 ap[4] = { aA.x, aA.y, aB.x, aB.y };
        #pragma unroll
        for (int rp = 0; rp < 4; rp++) {
            acc2[rp][0] = fma2(ap[rp], bd[0], acc2[rp][0]);
            acc2[rp][1] = fma2(ap[rp], bd[1], acc2[rp][1]);
            acc2[rp][2] = fma2(ap[rp], bd[2], acc2[rp][2]);
            acc2[rp][3] = fma2(ap[rp], bd[3], acc2[rp][3]);
        }
    }

    // ---- bias + silu -> sHT (transposed: [j][e]) ----
    {
        float4 bb = *(const float4*)&b1[j0];
        float bq[4] = { bb.x, bb.y, bb.z, bb.w };
        float h[8][4];
        #pragma unroll
        for (int rp = 0; rp < 4; rp++) {
            #pragma unroll
            for (int q = 0; q < 4; q++) {
                float x0, x1;
                unpack2(acc2[rp][q], x0, x1);
                x0 += bq[q]; x1 += bq[q];
                h[2 * rp + 0][q] = x0 / (1.0f + __expf(-x0));
                h[2 * rp + 1][q] = x1 / (1.0f + __expf(-x1));
            }
        }
        #pragma unroll
        for (int q = 0; q < 4; q++) {
            *(float4*)&sHT[(j0 + q) * T_STRIDE + eb] =
                make_float4(h[0][q], h[1][q], h[2][q], h[3][q]);
            *(float4*)&sHT[(j0 + q) * T_STRIDE + eb + 4] =
                make_float4(h[4][q], h[5][q], h[6][q], h[7][q]);
        }
    }

    // env pairs (constant across chunks)
    ulonglong2 eA = *(ulonglong2*)&sEnv[eb];
    ulonglong2 eB = *(ulonglong2*)&sEnv[eb + 4];
    u64 envp[4] = { eA.x, eA.y, eB.x, eB.y };

    float st0[8][4];   // split_0 stash in registers

    // ---- 3 chunks of GEMM2 + fused epilogue ----
    #pragma unroll
    for (int c = 0; c < 3; c++) {
        __syncthreads();   // sHT writes visible / prior sW reads done
        for (int i = tid; i < 128 * 32; i += 256) {
            int k = i >> 5, jj = (i & 31) * 4;
            *(float4*)&sW[k * 128 + jj] = *(const float4*)&W2[k * 384 + c * 128 + jj];
        }
        __syncthreads();

        #pragma unroll
        for (int rp = 0; rp < 4; rp++)
            acc2[rp][0] = acc2[rp][1] = acc2[rp][2] = acc2[rp][3] = 0ULL;

        #pragma unroll 8
        for (int k = 0; k < FEAT; k++) {
            float4 b4 = *(float4*)&sW[k * 128 + j0];
            u64 bd[4] = { dup2(b4.x), dup2(b4.y), dup2(b4.z), dup2(b4.w) };
            ulonglong2 aA = *(ulonglong2*)&sHT[k * T_STRIDE + eb];
            ulonglong2 aB = *(ulonglong2*)&sHT[k * T_STRIDE + eb + 4];
            u64 ap[4] = { aA.x, aA.y, aB.x, aB.y };
            #pragma unroll
            for (int rp = 0; rp < 4; rp++) {
                acc2[rp][0] = fma2(ap[rp], bd[0], acc2[rp][0]);
                acc2[rp][1] = fma2(ap[rp], bd[1], acc2[rp][1]);
                acc2[rp][2] = fma2(ap[rp], bd[2], acc2[rp][2]);
                acc2[rp][3] = fma2(ap[rp], bd[3], acc2[rp][3]);
            }
        }

        // ---- w_s = (rbf @ Wr + br) * env, packed over edge pairs ----
        u64 wsa[4][4];
        {
            float4 brv = *(const float4*)&br[c * 128 + j0];
            u64 b0 = dup2(brv.x), b1d = dup2(brv.y), b2d_ = dup2(brv.z), b3 = dup2(brv.w);
            #pragma unroll
            for (int rp = 0; rp < 4; rp++) {
                wsa[rp][0] = b0; wsa[rp][1] = b1d; wsa[rp][2] = b2d_; wsa[rp][3] = b3;
            }
            #pragma unroll 4
            for (int n = 0; n < NRBF; n++) {
                float4 w4 = *(const float4*)&Wr[n * 384 + c * 128 + j0];
                u64 wd[4] = { dup2(w4.x), dup2(w4.y), dup2(w4.z), dup2(w4.w) };
                ulonglong2 rA = *(ulonglong2*)&sRbfT[n * 64 + eb];
                ulonglong2 rB = *(ulonglong2*)&sRbfT[n * 64 + eb + 4];
                u64 rp_[4] = { rA.x, rA.y, rB.x, rB.y };
                #pragma unroll
                for (int rp = 0; rp < 4; rp++) {
                    wsa[rp][0] = fma2(rp_[rp], wd[0], wsa[rp][0]);
                    wsa[rp][1] = fma2(rp_[rp], wd[1], wsa[rp][1]);
                    wsa[rp][2] = fma2(rp_[rp], wd[2], wsa[rp][2]);
                    wsa[rp][3] = fma2(rp_[rp], wd[3], wsa[rp][3]);
                }
            }
        }

        // ---- inv = (gemm2 + b2) * (ws * env), then dispatch ----
        float4 b2v = *(const float4*)&b2[c * 128 + j0];
        u64 b2d[4] = { dup2(b2v.x), dup2(b2v.y), dup2(b2v.z), dup2(b2v.w) };

        #pragma unroll
        for (int rp = 0; rp < 4; rp++) {
            float iv[2][4];
            #pragma unroll
            for (int q = 0; q < 4; q++) {
                u64 inv = mul2(add2(acc2[rp][q], b2d[q]), mul2(wsa[rp][q], envp[rp]));
                unpack2(inv, iv[0][q], iv[1][q]);
            }
            #pragma unroll
            for (int h = 0; h < 2; h++) {
                int r = 2 * rp + h;
                int e = eb + r;
                if (c == 0) {
                    st0[r][0] = iv[h][0]; st0[r][1] = iv[h][1];
                    st0[r][2] = iv[h][2]; st0[r][3] = iv[h][3];
                } else if (c == 1) {
                    int bin = sBin[e];
                    red_add_v4(&g_acc_s[bin * FEAT + j0],
                               iv[h][0], iv[h][1], iv[h][2], iv[h][3]);
                } else {
                    int bin = sBin[e];
                    long eg = e0 + e;
                    const float4* vg = (const float4*)(v_i + ((long)eg * FEAT + j0) * 3);
                    float4 va = vg[0], vb = vg[1], vc = vg[2];
                    float v_[4][3];
                    v_[0][0] = va.x; v_[0][1] = va.y; v_[0][2] = va.z;
                    v_[1][0] = va.w; v_[1][1] = vb.x; v_[1][2] = vb.y;
                    v_[2][0] = vb.z; v_[2][1] = vb.w; v_[2][2] = vc.x;
                    v_[3][0] = vc.y; v_[3][1] = vc.z; v_[3][2] = vc.w;
                    #pragma unroll
                    for (int x = 0; x < 3; x++) {
                        float u = sUnitT[x * 64 + e];
                        red_add_v4(&g_acc_v[bin * 3 * FEAT + x * FEAT + j0],
                                   fmaf(iv[h][0], u, st0[r][0] * v_[0][x]),
                                   fmaf(iv[h][1], u, st0[r][1] * v_[1][x]),
                                   fmaf(iv[h][2], u, st0[r][2] * v_[2][x]),
                                   fmaf(iv[h][3], u, st0[r][3] * v_[3][x]));
                    }
                }
            }
        }
    }
}

__global__ void cmb_final(float* __restrict__ out) {
    int bin = blockIdx.x;
    int f   = threadIdx.x;
    float ic = 1.0f / fmaxf(g_cnt[bin], 1.0f);
    out[bin * FEAT + f] = g_acc_s[bin * FEAT + f] * ic;
    #pragma unroll
    for (int x = 0; x < 3; x++)
        out[NB * FEAT + bin * 384 + f * 3 + x] =
            g_acc_v[bin * 3 * FEAT + x * FEAT + f] * ic;
}

extern "C" void kernel_launch(void* const* d_in, const int* in_sizes, int n_in,
                              void* d_out, int out_size)
{
    const float* s_i     = (const float*)d_in[0];
    const float* v_i     = (const float*)d_in[1];
    const float* r_iI    = (const float*)d_in[2];
    const float* W1      = (const float*)d_in[3];
    const float* b1      = (const float*)d_in[4];
    const float* W2      = (const float*)d_in[5];
    const float* b2      = (const float*)d_in[6];
    const float* Wr      = (const float*)d_in[7];
    const float* br      = (const float*)d_in[8];
    const int*   mapping = (const int*)d_in[9];
    float* out = (float*)d_out;
    (void)in_sizes; (void)n_in; (void)out_size;

    cudaFuncSetAttribute((const void*)cmb_main,
                         cudaFuncAttributeMaxDynamicSharedMemorySize, SMEM_BYTES);

    cmb_zero<<<(NB * 3 * FEAT + 255) / 256, 256>>>();
    cmb_main<<<E_TOT / TM, 256, SMEM_BYTES>>>(s_i, v_i, r_iI, W1, b1, W2, b2,
                                              Wr, br, mapping);
    cmb_final<<<NB, FEAT>>>(out);
}

// round 5
// speedup vs baseline: 1.9326x; 1.5619x over previous
#include <cuda_runtime.h>
#include <cuda_bf16.h>
#include <math.h>

// ContractiveMessageBlock — Round 4: mma.sync (HMMA) bf16-split GEMMs.
// tcgen05 is unavailable (harness targets compute_103 without 'a' features).

#define E_TOT   200000
#define FEAT    128
#define TM      128
#define NBLK    ((E_TOT + TM - 1) / TM)   // 1563
#define NB      2000
#define NRBF    20
#define PI_OVER_CUT 0.62831853071795864769f

typedef unsigned long long u64;
typedef unsigned int u32;

// ---------------- f32x2 / misc helpers ----------------
__device__ __forceinline__ u64 fma2(u64 a, u64 b, u64 c) {
    u64 d; asm("fma.rn.f32x2 %0, %1, %2, %3;" : "=l"(d) : "l"(a), "l"(b), "l"(c)); return d;
}
__device__ __forceinline__ u64 mul2(u64 a, u64 b) {
    u64 d; asm("mul.rn.f32x2 %0, %1, %2;" : "=l"(d) : "l"(a), "l"(b)); return d;
}
__device__ __forceinline__ u64 add2(u64 a, u64 b) {
    u64 d; asm("add.rn.f32x2 %0, %1, %2;" : "=l"(d) : "l"(a), "l"(b)); return d;
}
__device__ __forceinline__ u64 dup2(float x) {
    u64 d; asm("mov.b64 %0, {%1, %1};" : "=l"(d) : "f"(x)); return d;
}
__device__ __forceinline__ u64 pk2(float a, float b) {
    u64 d; asm("mov.b64 %0, {%1, %2};" : "=l"(d) : "f"(a), "f"(b)); return d;
}
__device__ __forceinline__ void unpack2(u64 a, float& lo, float& hi) {
    asm("mov.b64 {%0, %1}, %2;" : "=f"(lo), "=f"(hi) : "l"(a));
}
__device__ __forceinline__ void red_add_v4(float* p, float a, float b, float c, float d) {
    asm volatile("red.global.add.v4.f32 [%0], {%1, %2, %3, %4};"
                 :: "l"(p), "f"(a), "f"(b), "f"(c), "f"(d) : "memory");
}
__device__ __forceinline__ u32 smem_u32(const void* p) {
    u32 a; asm("{ .reg .u64 t; cvta.to.shared.u64 t, %1; cvt.u32.u64 %0, t; }"
               : "=r"(a) : "l"(p));
    return a;
}
__device__ __forceinline__ void split2(float x, float y, u32& hi, u32& lo) {
    __nv_bfloat162 h = __floats2bfloat162_rn(x, y);
    float rx = x - __bfloat162float(h.x);
    float ry = y - __bfloat162float(h.y);
    __nv_bfloat162 l = __floats2bfloat162_rn(rx, ry);
    hi = *(u32*)&h; lo = *(u32*)&l;
}

// ---------------- mma / ldmatrix ----------------
__device__ __forceinline__ void ldsm4(u32* r, u32 addr) {
    asm volatile("ldmatrix.sync.aligned.m8n8.x4.shared.b16 {%0,%1,%2,%3}, [%4];"
                 : "=r"(r[0]), "=r"(r[1]), "=r"(r[2]), "=r"(r[3]) : "r"(addr));
}
__device__ __forceinline__ void mma16816(float* d, const u32* a, u32 b0, u32 b1) {
    asm volatile(
        "mma.sync.aligned.m16n8k16.row.col.f32.bf16.bf16.f32 "
        "{%0,%1,%2,%3}, {%4,%5,%6,%7}, {%8,%9}, {%0,%1,%2,%3};"
        : "+f"(d[0]), "+f"(d[1]), "+f"(d[2]), "+f"(d[3])
        : "r"(a[0]), "r"(a[1]), "r"(a[2]), "r"(a[3]), "r"(b0), "r"(b1));
}

// bf16 tile [128 rows][128 k]: 16B granules, XOR swizzle for conflict-free ldmatrix.
// byte offset of granule (row, kg): kg = k/8.
__device__ __host__ __forceinline__ int toff(int row, int kg) {
    return row * 256 + (((kg ^ (row & 7)) & 15) << 4);
}
// fp32 scratch [128 e][128 c], word index with 4-word-granule XOR swizzle.
__device__ __forceinline__ int scr_w(int e, int c) {
    return e * 128 + (((((c >> 2)) ^ (e & 7)) & 31) << 2) + (c & 3);
}

// ---------------- global scratch ----------------
__device__ __align__(16) float g_acc_s[NB * FEAT];      // [bin][f]
__device__ __align__(16) float g_acc_v[NB * 3 * FEAT];  // [bin][x][f]
__device__ float g_cnt[NB];
__device__ __align__(16) float g_split0[(size_t)E_TOT * FEAT];   // chunk-0 stash
__device__ __align__(16) unsigned char g_W1hi[32768], g_W1lo[32768];
__device__ __align__(16) unsigned char g_W2hi[3 * 32768], g_W2lo[3 * 32768];

// ---------------- smem offsets (bytes) ----------------
#define OFF_AHI  0        // 32768  A then H, bf16 hi
#define OFF_ALO  32768    // 32768  A then H, bf16 lo
#define OFF_WHI  65536    // 32768  current W tile hi
#define OFF_WLO  98304    // 32768  current W tile lo
#define OFF_SCR  131072   // 65536  fp32 D dump [128][128]
#define OFF_RBF  196608   // 10240  rbf [20][128]
#define OFF_UNIT 206848   // 1536   unit [3][128]
#define OFF_ENV  208384   // 512
#define OFF_BIN  208896   // 512 (int)
#define SMEM_BYTES 209408

__global__ void cmb_zero() {
    int i = blockIdx.x * 256 + threadIdx.x;
    if (i < NB * FEAT)     g_acc_s[i] = 0.0f;
    if (i < NB * 3 * FEAT) g_acc_v[i] = 0.0f;
    if (i < NB)            g_cnt[i]   = 0.0f;
}

// W1/W2 -> bf16 hi/lo tiles in swizzled [n][k] layout (B operand, TN gemm).
__global__ void cmb_prep(const float* __restrict__ W1, const float* __restrict__ W2) {
    int i = blockIdx.x * 256 + threadIdx.x;     // 0..65535
    if (i < 16384) {
        int n = i & 127, k = i >> 7;
        float v = W1[k * 128 + n];
        __nv_bfloat16 h = __float2bfloat16(v);
        float lo = v - __bfloat162float(h);
        int off = toff(n, k >> 3) + (k & 7) * 2;
        *(__nv_bfloat16*)(g_W1hi + off) = h;
        *(__nv_bfloat16*)(g_W1lo + off) = __float2bfloat16(lo);
    } else if (i < 65536) {
        int r = i - 16384;
        int c = r >> 14;
        int t = r & 16383;
        int n = t & 127, k = t >> 7;
        float v = W2[k * 384 + c * 128 + n];
        __nv_bfloat16 h = __float2bfloat16(v);
        float lo = v - __bfloat162float(h);
        int off = c * 32768 + toff(n, k >> 3) + (k & 7) * 2;
        *(__nv_bfloat16*)(g_W2hi + off) = h;
        *(__nv_bfloat16*)(g_W2lo + off) = __float2bfloat16(lo);
    }
}

// 3-pass bf16-split GEMM: acc[128 rows of warp stripe][128 cols] += A*B
__device__ __forceinline__ void gemm_tile(u32 aHi, u32 aLo, u32 bHi, u32 bLo,
                                          int m0, int lane, float acc[16][4]) {
    const int r  = lane & 7;
    const int hf = (lane >> 3) & 1;
    const int kq = lane >> 4;
    const int arow = m0 + hf * 8 + r;
    #pragma unroll 2
    for (int ks = 0; ks < 8; ks++) {
        int kg = ks * 2 + kq;
        u32 ah[4], al[4];
        u32 aoff = (u32)toff(arow, kg);
        ldsm4(ah, aHi + aoff);
        ldsm4(al, aLo + aoff);
        #pragma unroll
        for (int ng = 0; ng < 8; ng++) {
            u32 bh[4], bl[4];
            u32 boff = (u32)toff(ng * 16 + hf * 8 + r, kg);
            ldsm4(bh, bHi + boff);
            ldsm4(bl, bLo + boff);
            mma16816(acc[2 * ng],     ah, bh[0], bh[2]);
            mma16816(acc[2 * ng + 1], ah, bh[1], bh[3]);
            mma16816(acc[2 * ng],     ah, bl[0], bl[2]);
            mma16816(acc[2 * ng + 1], ah, bl[1], bl[3]);
            mma16816(acc[2 * ng],     al, bh[0], bh[2]);
            mma16816(acc[2 * ng + 1], al, bh[1], bh[3]);
        }
    }
}

__device__ __forceinline__ void dump_all(float* scr, const float acc[16][4],
                                         int m0, int lane) {
    const int r0 = m0 + (lane >> 2);
    const int cb = (lane & 3) * 2;
    #pragma unroll
    for (int ng = 0; ng < 8; ng++)
        #pragma unroll
        for (int s = 0; s < 2; s++) {
            int c = ng * 16 + s * 8 + cb;
            const float* a = acc[2 * ng + s];
            *(float2*)&scr[scr_w(r0, c)]     = make_float2(a[0], a[1]);
            *(float2*)&scr[(size_t)scr_w(r0 + 8, c)] = make_float2(a[2], a[3]);
        }
}

__global__ void __launch_bounds__(256, 1)
cmb_main(const float* __restrict__ s_i, const float* __restrict__ v_i,
         const float* __restrict__ r_iI, const float* __restrict__ b1,
         const float* __restrict__ b2, const float* __restrict__ Wr_g,
         const float* __restrict__ br, const int* __restrict__ mapping)
{
    extern __shared__ char smem[];
    const u32 sb = smem_u32(smem);
    float* sScr  = (float*)(smem + OFF_SCR);
    float* sRbfT = (float*)(smem + OFF_RBF);
    float* sUnit = (float*)(smem + OFF_UNIT);
    float* sEnv  = (float*)(smem + OFF_ENV);
    int*   sBin  = (int*)(smem + OFF_BIN);

    const int tid  = threadIdx.x;
    const int wid  = tid >> 5;
    const int lane = tid & 31;
    const int m0   = wid * 16;               // warp's edge-row stripe
    const long e0  = (long)blockIdx.x * TM;
    const int nvalid = (int)min((long)TM, (long)E_TOT - e0);

    // ---- A tile: s_i -> bf16 hi/lo swizzled ----
    for (int i = tid; i < 2048; i += 256) {
        int row = i >> 4, kg = i & 15;
        float4 va, vb;
        if (row < nvalid) {
            const float4* g = (const float4*)(s_i + ((size_t)(e0 + row)) * FEAT + kg * 8);
            va = g[0]; vb = g[1];
        } else {
            va = make_float4(0.f, 0.f, 0.f, 0.f); vb = va;
        }
        u32 h0, l0, h1, l1, h2, l2, h3, l3;
        split2(va.x, va.y, h0, l0); split2(va.z, va.w, h1, l1);
        split2(vb.x, vb.y, h2, l2); split2(vb.z, vb.w, h3, l3);
        int off = toff(row, kg);
        *(uint4*)(smem + OFF_AHI + off) = make_uint4(h0, h1, h2, h3);
        *(uint4*)(smem + OFF_ALO + off) = make_uint4(l0, l1, l2, l3);
    }
    // ---- W1 hi/lo linear copy ----
    {
        const float4* wh = (const float4*)g_W1hi;
        const float4* wl = (const float4*)g_W1lo;
        float4* dh = (float4*)(smem + OFF_WHI);
        float4* dl = (float4*)(smem + OFF_WLO);
        for (int i = tid; i < 2048; i += 256) { dh[i] = wh[i]; dl[i] = wl[i]; }
    }
    // ---- per-edge preprocess ----
    if (tid < TM) {
        int e = tid;
        if (e < nvalid) {
            long eg = e0 + e;
            float r0 = r_iI[eg * 3 + 0], r1 = r_iI[eg * 3 + 1], r2 = r_iI[eg * 3 + 2];
            float d = sqrtf(r0 * r0 + r1 * r1 + r2 * r2 + 3e-8f);
            float id = 1.0f / d;
            sUnit[0 * 128 + e] = r0 * id;
            sUnit[1 * 128 + e] = r1 * id;
            sUnit[2 * 128 + e] = r2 * id;
            sEnv[e] = (d < 5.0f) ? 0.5f * (cosf(PI_OVER_CUT * d) + 1.0f) : 0.0f;
            float ang = PI_OVER_CUT * d;
            #pragma unroll
            for (int n = 0; n < NRBF; n++)
                sRbfT[n * 128 + e] = sinf((float)(n + 1) * ang) * id;
            int b = mapping[eg];
            sBin[e] = b;
            atomicAdd(&g_cnt[b], 1.0f);
        } else {
            sUnit[e] = sUnit[128 + e] = sUnit[256 + e] = 0.0f;
            sEnv[e] = 0.0f; sBin[e] = 0;
            #pragma unroll
            for (int n = 0; n < NRBF; n++) sRbfT[n * 128 + e] = 0.0f;
        }
    }
    __syncthreads();

    float acc[16][4];

    // ---- GEMM1 ----
    #pragma unroll
    for (int q = 0; q < 16; q++)
        acc[q][0] = acc[q][1] = acc[q][2] = acc[q][3] = 0.0f;
    gemm_tile(sb + OFF_AHI, sb + OFF_ALO, sb + OFF_WHI, sb + OFF_WLO, m0, lane, acc);
    dump_all(sScr, acc, m0, lane);
    __syncthreads();

    // ---- silu(D1 + b1) -> H bf16 hi/lo (overwrite A tiles) ----
    {
        const int j0  = (tid & 31) * 4;
        const int ebl = (tid >> 5) * 16;
        float4 bb = *(const float4*)&b1[j0];
        #pragma unroll 4
        for (int e = 0; e < 16; e++) {
            int ei = ebl + e;
            float4 d = *(float4*)&sScr[scr_w(ei, j0)];
            float x0 = d.x + bb.x, x1 = d.y + bb.y, x2 = d.z + bb.z, x3 = d.w + bb.w;
            float s0 = x0 / (1.0f + __expf(-x0));
            float s1 = x1 / (1.0f + __expf(-x1));
            float s2 = x2 / (1.0f + __expf(-x2));
            float s3 = x3 / (1.0f + __expf(-x3));
            u32 hA, lA, hB, lB;
            split2(s0, s1, hA, lA); split2(s2, s3, hB, lB);
            int off = toff(ei, j0 >> 3) + (j0 & 7) * 2;
            *(uint2*)(smem + OFF_AHI + off) = make_uint2(hA, hB);
            *(uint2*)(smem + OFF_ALO + off) = make_uint2(lA, lB);
        }
    }

    // ---- GEMM2 chunks + fused epilogue ----
    #pragma unroll
    for (int c = 0; c < 3; c++) {
        __syncthreads();   // H writes / prev epilogue done; W buffers free
        {
            const float4* wh = (const float4*)(g_W2hi + c * 32768);
            const float4* wl = (const float4*)(g_W2lo + c * 32768);
            float4* dh = (float4*)(smem + OFF_WHI);
            float4* dl = (float4*)(smem + OFF_WLO);
            for (int i = tid; i < 2048; i += 256) { dh[i] = wh[i]; dl[i] = wl[i]; }
        }
        __syncthreads();

        #pragma unroll
        for (int q = 0; q < 16; q++)
            acc[q][0] = acc[q][1] = acc[q][2] = acc[q][3] = 0.0f;
        gemm_tile(sb + OFF_AHI, sb + OFF_ALO, sb + OFF_WHI, sb + OFF_WLO, m0, lane, acc);
        dump_all(sScr, acc, m0, lane);
        __syncthreads();

        // ---- epilogue: filter + split dispatch, 16 edges x 4 cols per thread ----
        {
            const int j0  = (tid & 31) * 4;
            const int ebl = (tid >> 5) * 16;
            u64 wra[NRBF], wrb[NRBF];
            #pragma unroll
            for (int n = 0; n < NRBF; n++) {
                float4 w = *(const float4*)&Wr_g[n * 384 + c * 128 + j0];
                wra[n] = pk2(w.x, w.y); wrb[n] = pk2(w.z, w.w);
            }
            float4 b2v = *(const float4*)&b2[c * 128 + j0];
            float4 brv = *(const float4*)&br[c * 128 + j0];
            u64 b2a = pk2(b2v.x, b2v.y), b2b = pk2(b2v.z, b2v.w);
            u64 bra = pk2(brv.x, brv.y), brb = pk2(brv.z, brv.w);

            #pragma unroll 2
            for (int e = 0; e < 16; e++) {
                int ei = ebl + e;
                u64 w0 = bra, w1 = brb;
                #pragma unroll
                for (int n = 0; n < NRBF; n++) {
                    u64 f = dup2(sRbfT[n * 128 + ei]);
                    w0 = fma2(f, wra[n], w0);
                    w1 = fma2(f, wrb[n], w1);
                }
                float4 d = *(float4*)&sScr[scr_w(ei, j0)];
                u64 envd = dup2(sEnv[ei]);
                u64 i01 = mul2(add2(pk2(d.x, d.y), b2a), mul2(w0, envd));
                u64 i23 = mul2(add2(pk2(d.z, d.w), b2b), mul2(w1, envd));
                float i0, i1, i2, i3;
                unpack2(i01, i0, i1); unpack2(i23, i2, i3);

                if (ei < nvalid) {
                    if (c == 0) {
                        *(float4*)&g_split0[(size_t)(e0 + ei) * FEAT + j0] =
                            make_float4(i0, i1, i2, i3);
                    } else if (c == 1) {
                        int bin = sBin[ei];
                        red_add_v4(&g_acc_s[bin * FEAT + j0], i0, i1, i2, i3);
                    } else {
                        int bin = sBin[ei];
                        float4 s0 = *(const float4*)&g_split0[(size_t)(e0 + ei) * FEAT + j0];
                        const float4* vg =
                            (const float4*)(v_i + ((size_t)(e0 + ei) * FEAT + j0) * 3);
                        float4 va = vg[0], vb = vg[1], vc2 = vg[2];
                        float vf[12] = { va.x, va.y, va.z, va.w,
                                         vb.x, vb.y, vb.z, vb.w,
                                         vc2.x, vc2.y, vc2.z, vc2.w };
                        float uu[3] = { sUnit[ei], sUnit[128 + ei], sUnit[256 + ei] };
                        #pragma unroll
                        for (int x = 0; x < 3; x++)
                            red_add_v4(&g_acc_v[bin * 3 * FEAT + x * FEAT + j0],
                                fmaf(i0, uu[x], s0.x * vf[0 + x]),
                                fmaf(i1, uu[x], s0.y * vf[3 + x]),
                                fmaf(i2, uu[x], s0.z * vf[6 + x]),
                                fmaf(i3, uu[x], s0.w * vf[9 + x]));
                    }
                }
            }
        }
    }
}

__global__ void cmb_final(float* __restrict__ out) {
    int bin = blockIdx.x;
    int f   = threadIdx.x;
    float ic = 1.0f / fmaxf(g_cnt[bin], 1.0f);
    out[bin * FEAT + f] = g_acc_s[bin * FEAT + f] * ic;
    #pragma unroll
    for (int x = 0; x < 3; x++)
        out[NB * FEAT + bin * 384 + f * 3 + x] =
            g_acc_v[bin * 3 * FEAT + x * FEAT + f] * ic;
}

extern "C" void kernel_launch(void* const* d_in, const int* in_sizes, int n_in,
                              void* d_out, int out_size)
{
    const float* s_i     = (const float*)d_in[0];
    const float* v_i     = (const float*)d_in[1];
    const float* r_iI    = (const float*)d_in[2];
    const float* W1      = (const float*)d_in[3];
    const float* b1      = (const float*)d_in[4];
    const float* W2      = (const float*)d_in[5];
    const float* b2      = (const float*)d_in[6];
    const float* Wr      = (const float*)d_in[7];
    const float* br      = (const float*)d_in[8];
    const int*   mapping = (const int*)d_in[9];
    float* out = (float*)d_out;
    (void)in_sizes; (void)n_in; (void)out_size;

    cudaFuncSetAttribute((const void*)cmb_main,
                         cudaFuncAttributeMaxDynamicSharedMemorySize, SMEM_BYTES);

    cmb_prep<<<256, 256>>>(W1, W2);
    cmb_zero<<<(NB * 3 * FEAT + 255) / 256, 256>>>();
    cmb_main<<<NBLK, 256, SMEM_BYTES>>>(s_i, v_i, r_iI, b1, b2, Wr, br, mapping);
    cmb_final<<<NB, FEAT>>>(out);
}

// round 6
// speedup vs baseline: 1.9937x; 1.0316x over previous
#include <cuda_runtime.h>
#include <cuda_bf16.h>
#include <math.h>

// ContractiveMessageBlock — Round 5: HMMA bf16-split GEMMs, register split0,
// cp.async W prefetch overlapped with epilogue, warp-local dump/epilogue.

#define E_TOT   200000
#define FEAT    128
#define TM      128
#define NBLK    ((E_TOT + TM - 1) / TM)   // 1563
#define NB      2000
#define NRBF    20
#define PI_OVER_CUT 0.62831853071795864769f

typedef unsigned long long u64;
typedef unsigned int u32;

// ---------------- f32x2 / misc helpers ----------------
__device__ __forceinline__ u64 fma2(u64 a, u64 b, u64 c) {
    u64 d; asm("fma.rn.f32x2 %0, %1, %2, %3;" : "=l"(d) : "l"(a), "l"(b), "l"(c)); return d;
}
__device__ __forceinline__ u64 mul2(u64 a, u64 b) {
    u64 d; asm("mul.rn.f32x2 %0, %1, %2;" : "=l"(d) : "l"(a), "l"(b)); return d;
}
__device__ __forceinline__ u64 add2(u64 a, u64 b) {
    u64 d; asm("add.rn.f32x2 %0, %1, %2;" : "=l"(d) : "l"(a), "l"(b)); return d;
}
__device__ __forceinline__ u64 dup2(float x) {
    u64 d; asm("mov.b64 %0, {%1, %1};" : "=l"(d) : "f"(x)); return d;
}
__device__ __forceinline__ u64 pk2(float a, float b) {
    u64 d; asm("mov.b64 %0, {%1, %2};" : "=l"(d) : "f"(a), "f"(b)); return d;
}
__device__ __forceinline__ void unpack2(u64 a, float& lo, float& hi) {
    asm("mov.b64 {%0, %1}, %2;" : "=f"(lo), "=f"(hi) : "l"(a));
}
__device__ __forceinline__ void red_add_v4(float* p, float a, float b, float c, float d) {
    asm volatile("red.global.add.v4.f32 [%0], {%1, %2, %3, %4};"
                 :: "l"(p), "f"(a), "f"(b), "f"(c), "f"(d) : "memory");
}
__device__ __forceinline__ u32 smem_u32(const void* p) {
    u32 a; asm("{ .reg .u64 t; cvta.to.shared.u64 t, %1; cvt.u32.u64 %0, t; }"
               : "=r"(a) : "l"(p));
    return a;
}
__device__ __forceinline__ void split2(float x, float y, u32& hi, u32& lo) {
    __nv_bfloat162 h = __floats2bfloat162_rn(x, y);
    float rx = x - __bfloat162float(h.x);
    float ry = y - __bfloat162float(h.y);
    __nv_bfloat162 l = __floats2bfloat162_rn(rx, ry);
    hi = *(u32*)&h; lo = *(u32*)&l;
}
__device__ __forceinline__ void cpa16(u32 s, const void* g) {
    asm volatile("cp.async.cg.shared.global [%0], [%1], 16;" :: "r"(s), "l"(g));
}
__device__ __forceinline__ void cpa_commit() {
    asm volatile("cp.async.commit_group;" ::: "memory");
}
__device__ __forceinline__ void cpa_wait0() {
    asm volatile("cp.async.wait_group 0;" ::: "memory");
}

// ---------------- mma / ldmatrix ----------------
__device__ __forceinline__ void ldsm4(u32* r, u32 addr) {
    asm volatile("ldmatrix.sync.aligned.m8n8.x4.shared.b16 {%0,%1,%2,%3}, [%4];"
                 : "=r"(r[0]), "=r"(r[1]), "=r"(r[2]), "=r"(r[3]) : "r"(addr));
}
__device__ __forceinline__ void mma16816(float* d, const u32* a, u32 b0, u32 b1) {
    asm volatile(
        "mma.sync.aligned.m16n8k16.row.col.f32.bf16.bf16.f32 "
        "{%0,%1,%2,%3}, {%4,%5,%6,%7}, {%8,%9}, {%0,%1,%2,%3};"
        : "+f"(d[0]), "+f"(d[1]), "+f"(d[2]), "+f"(d[3])
        : "r"(a[0]), "r"(a[1]), "r"(a[2]), "r"(a[3]), "r"(b0), "r"(b1));
}

// bf16 tile [128 rows][128 k]: 16B granules, XOR swizzle.
__device__ __host__ __forceinline__ int toff(int row, int kg) {
    return row * 256 + (((kg ^ (row & 7)) & 15) << 4);
}
// fp32 scratch [128 e][128 c], word index with 4-word-granule XOR swizzle.
__device__ __forceinline__ int scr_w(int e, int c) {
    return e * 128 + (((((c >> 2)) ^ (e & 7)) & 31) << 2) + (c & 3);
}

// ---------------- global scratch ----------------
__device__ __align__(16) float g_acc_s[NB * FEAT];      // [bin][f]
__device__ __align__(16) float g_acc_v[NB * 3 * FEAT];  // [bin][x][f]
__device__ float g_cnt[NB];
__device__ __align__(16) unsigned char g_W1hi[32768], g_W1lo[32768];
__device__ __align__(16) unsigned char g_W2hi[3 * 32768], g_W2lo[3 * 32768];

// ---------------- smem offsets (bytes) ----------------
#define OFF_AHI  0        // 32768  A then H, bf16 hi
#define OFF_ALO  32768    // 32768  A then H, bf16 lo
#define OFF_WHI  65536    // 32768  current W tile hi
#define OFF_WLO  98304    // 32768  current W tile lo
#define OFF_SCR  131072   // 65536  fp32 D dump [128][128]
#define OFF_RBF  196608   // 10240  rbf [20][128]
#define OFF_UNIT 206848   // 1536   unit [3][128]
#define OFF_ENV  208384   // 512
#define OFF_BIN  208896   // 512 (int)
#define SMEM_BYTES 209408

__global__ void cmb_zero() {
    int i = blockIdx.x * 256 + threadIdx.x;
    if (i < NB * FEAT)     g_acc_s[i] = 0.0f;
    if (i < NB * 3 * FEAT) g_acc_v[i] = 0.0f;
    if (i < NB)            g_cnt[i]   = 0.0f;
}

// W1/W2 -> bf16 hi/lo tiles in swizzled [n][k] layout (B operand, TN gemm).
__global__ void cmb_prep(const float* __restrict__ W1, const float* __restrict__ W2) {
    int i = blockIdx.x * 256 + threadIdx.x;     // 0..65535
    if (i < 16384) {
        int n = i & 127, k = i >> 7;
        float v = W1[k * 128 + n];
        __nv_bfloat16 h = __float2bfloat16(v);
        float lo = v - __bfloat162float(h);
        int off = toff(n, k >> 3) + (k & 7) * 2;
        *(__nv_bfloat16*)(g_W1hi + off) = h;
        *(__nv_bfloat16*)(g_W1lo + off) = __float2bfloat16(lo);
    } else if (i < 65536) {
        int r = i - 16384;
        int c = r >> 14;
        int t = r & 16383;
        int n = t & 127, k = t >> 7;
        float v = W2[k * 384 + c * 128 + n];
        __nv_bfloat16 h = __float2bfloat16(v);
        float lo = v - __bfloat162float(h);
        int off = c * 32768 + toff(n, k >> 3) + (k & 7) * 2;
        *(__nv_bfloat16*)(g_W2hi + off) = h;
        *(__nv_bfloat16*)(g_W2lo + off) = __float2bfloat16(lo);
    }
}

// Issue cp.async for one W tile pair (hi+lo, 32KB each).
__device__ __forceinline__ void copyW_async(u32 sb, const unsigned char* ghi,
                                            const unsigned char* glo, int tid) {
    u32 dh = sb + OFF_WHI, dl = sb + OFF_WLO;
    #pragma unroll
    for (int t = 0; t < 8; t++) {
        int i = tid + t * 256;
        cpa16(dh + i * 16, ghi + i * 16);
        cpa16(dl + i * 16, glo + i * 16);
    }
    cpa_commit();
}

// 3-pass bf16-split GEMM: acc[16][4] over warp stripe.
__device__ __forceinline__ void gemm_tile(u32 aHi, u32 aLo, u32 bHi, u32 bLo,
                                          int m0, int lane, float acc[16][4]) {
    const int r  = lane & 7;
    const int hf = (lane >> 3) & 1;
    const int kq = lane >> 4;
    const int arow = m0 + hf * 8 + r;
    #pragma unroll 2
    for (int ks = 0; ks < 8; ks++) {
        int kg = ks * 2 + kq;
        u32 ah[4], al[4];
        u32 aoff = (u32)toff(arow, kg);
        ldsm4(ah, aHi + aoff);
        ldsm4(al, aLo + aoff);
        #pragma unroll
        for (int ng = 0; ng < 8; ng++) {
            u32 bh[4], bl[4];
            u32 boff = (u32)toff(ng * 16 + hf * 8 + r, kg);
            ldsm4(bh, bHi + boff);
            ldsm4(bl, bLo + boff);
            mma16816(acc[2 * ng],     ah, bh[0], bh[2]);
            mma16816(acc[2 * ng + 1], ah, bh[1], bh[3]);
            mma16816(acc[2 * ng],     ah, bl[0], bl[2]);
            mma16816(acc[2 * ng + 1], ah, bl[1], bl[3]);
            mma16816(acc[2 * ng],     al, bh[0], bh[2]);
            mma16816(acc[2 * ng + 1], al, bh[1], bh[3]);
        }
    }
}

__device__ __forceinline__ void dump_all(float* scr, const float acc[16][4],
                                         int m0, int lane) {
    const int r0 = m0 + (lane >> 2);
    const int cb = (lane & 3) * 2;
    #pragma unroll
    for (int ng = 0; ng < 8; ng++)
        #pragma unroll
        for (int s = 0; s < 2; s++) {
            int c = ng * 16 + s * 8 + cb;
            const float* a = acc[2 * ng + s];
            *(float2*)&scr[scr_w(r0, c)]     = make_float2(a[0], a[1]);
            *(float2*)&scr[scr_w(r0 + 8, c)] = make_float2(a[2], a[3]);
        }
}

// Fused epilogue for chunk C. Fully unrolled over 16 edges so st0 stays in regs.
template <int C>
__device__ __forceinline__ void epilogue(
    const float* sScr, const float* sRbfT, const float* sUnit,
    const float* sEnv, const int* sBin,
    const float* __restrict__ v_i, const float* __restrict__ Wr_g,
    const float* __restrict__ b2, const float* __restrict__ br,
    long e0, int nvalid, int tid, float st0[16][4])
{
    const int j0  = (tid & 31) * 4;
    const int ebl = (tid >> 5) * 16;
    u64 wra[NRBF], wrb[NRBF];
    #pragma unroll
    for (int n = 0; n < NRBF; n++) {
        float4 w = *(const float4*)&Wr_g[n * 384 + C * 128 + j0];
        wra[n] = pk2(w.x, w.y); wrb[n] = pk2(w.z, w.w);
    }
    float4 b2v = *(const float4*)&b2[C * 128 + j0];
    float4 brv = *(const float4*)&br[C * 128 + j0];
    u64 b2a = pk2(b2v.x, b2v.y), b2b = pk2(b2v.z, b2v.w);
    u64 bra = pk2(brv.x, brv.y), brb = pk2(brv.z, brv.w);

    #pragma unroll
    for (int e = 0; e < 16; e++) {
        int ei = ebl + e;
        u64 w0 = bra, w1 = brb;
        #pragma unroll
        for (int n = 0; n < NRBF; n++) {
            u64 f = dup2(sRbfT[n * 128 + ei]);
            w0 = fma2(f, wra[n], w0);
            w1 = fma2(f, wrb[n], w1);
        }
        float4 d = *(const float4*)&sScr[scr_w(ei, j0)];
        u64 envd = dup2(sEnv[ei]);
        u64 i01 = mul2(add2(pk2(d.x, d.y), b2a), mul2(w0, envd));
        u64 i23 = mul2(add2(pk2(d.z, d.w), b2b), mul2(w1, envd));
        float i0, i1, i2, i3;
        unpack2(i01, i0, i1); unpack2(i23, i2, i3);

        if (C == 0) {
            st0[e][0] = i0; st0[e][1] = i1; st0[e][2] = i2; st0[e][3] = i3;
        } else if (C == 1) {
            if (ei < nvalid) {
                int bin = sBin[ei];
                red_add_v4(&g_acc_s[bin * FEAT + j0], i0, i1, i2, i3);
            }
        } else {
            if (ei < nvalid) {
                int bin = sBin[ei];
                const float4* vg =
                    (const float4*)(v_i + ((size_t)(e0 + ei) * FEAT + j0) * 3);
                float4 va = vg[0], vb = vg[1], vc2 = vg[2];
                float vf[12] = { va.x, va.y, va.z, va.w,
                                 vb.x, vb.y, vb.z, vb.w,
                                 vc2.x, vc2.y, vc2.z, vc2.w };
                float uu[3] = { sUnit[ei], sUnit[128 + ei], sUnit[256 + ei] };
                #pragma unroll
                for (int x = 0; x < 3; x++)
                    red_add_v4(&g_acc_v[bin * 3 * FEAT + x * FEAT + j0],
                        fmaf(i0, uu[x], st0[e][0] * vf[0 + x]),
                        fmaf(i1, uu[x], st0[e][1] * vf[3 + x]),
                        fmaf(i2, uu[x], st0[e][2] * vf[6 + x]),
                        fmaf(i3, uu[x], st0[e][3] * vf[9 + x]));
            }
        }
    }
}

__global__ void __launch_bounds__(256, 1)
cmb_main(const float* __restrict__ s_i, const float* __restrict__ v_i,
         const float* __restrict__ r_iI, const float* __restrict__ b1,
         const float* __restrict__ b2, const float* __restrict__ Wr_g,
         const float* __restrict__ br, const int* __restrict__ mapping)
{
    extern __shared__ char smem[];
    const u32 sb = smem_u32(smem);
    float* sScr  = (float*)(smem + OFF_SCR);
    float* sRbfT = (float*)(smem + OFF_RBF);
    float* sUnit = (float*)(smem + OFF_UNIT);
    float* sEnv  = (float*)(smem + OFF_ENV);
    int*   sBin  = (int*)(smem + OFF_BIN);

    const int tid  = threadIdx.x;
    const int wid  = tid >> 5;
    const int lane = tid & 31;
    const int m0   = wid * 16;
    const long e0  = (long)blockIdx.x * TM;
    const int nvalid = (int)min((long)TM, (long)E_TOT - e0);

    // ---- W1 prefetch (cp.async) ----
    copyW_async(sb, g_W1hi, g_W1lo, tid);

    // ---- A tile: s_i -> bf16 hi/lo swizzled ----
    for (int i = tid; i < 2048; i += 256) {
        int row = i >> 4, kg = i & 15;
        float4 va, vb;
        if (row < nvalid) {
            const float4* g = (const float4*)(s_i + ((size_t)(e0 + row)) * FEAT + kg * 8);
            va = g[0]; vb = g[1];
        } else {
            va = make_float4(0.f, 0.f, 0.f, 0.f); vb = va;
        }
        u32 h0, l0, h1, l1, h2, l2, h3, l3;
        split2(va.x, va.y, h0, l0); split2(va.z, va.w, h1, l1);
        split2(vb.x, vb.y, h2, l2); split2(vb.z, vb.w, h3, l3);
        int off = toff(row, kg);
        *(uint4*)(smem + OFF_AHI + off) = make_uint4(h0, h1, h2, h3);
        *(uint4*)(smem + OFF_ALO + off) = make_uint4(l0, l1, l2, l3);
    }
    // ---- per-edge preprocess ----
    if (tid < TM) {
        int e = tid;
        if (e < nvalid) {
            long eg = e0 + e;
            float r0 = r_iI[eg * 3 + 0], r1 = r_iI[eg * 3 + 1], r2 = r_iI[eg * 3 + 2];
            float d = sqrtf(r0 * r0 + r1 * r1 + r2 * r2 + 3e-8f);
            float id = 1.0f / d;
            sUnit[0 * 128 + e] = r0 * id;
            sUnit[1 * 128 + e] = r1 * id;
            sUnit[2 * 128 + e] = r2 * id;
            sEnv[e] = (d < 5.0f) ? 0.5f * (cosf(PI_OVER_CUT * d) + 1.0f) : 0.0f;
            float ang = PI_OVER_CUT * d;
            #pragma unroll
            for (int n = 0; n < NRBF; n++)
                sRbfT[n * 128 + e] = sinf((float)(n + 1) * ang) * id;
            int b = mapping[eg];
            sBin[e] = b;
            atomicAdd(&g_cnt[b], 1.0f);
        } else {
            sUnit[e] = sUnit[128 + e] = sUnit[256 + e] = 0.0f;
            sEnv[e] = 0.0f; sBin[e] = 0;
            #pragma unroll
            for (int n = 0; n < NRBF; n++) sRbfT[n * 128 + e] = 0.0f;
        }
    }
    cpa_wait0();
    __syncthreads();

    float acc[16][4];
    float st0[16][4];

    // ---- GEMM1 ----
    #pragma unroll
    for (int q = 0; q < 16; q++)
        acc[q][0] = acc[q][1] = acc[q][2] = acc[q][3] = 0.0f;
    gemm_tile(sb + OFF_AHI, sb + OFF_ALO, sb + OFF_WHI, sb + OFF_WLO, m0, lane, acc);
    __syncthreads();                       // all warps done reading W1
    copyW_async(sb, g_W2hi, g_W2lo, tid);  // prefetch W2[0] under dump+silu
    dump_all(sScr, acc, m0, lane);
    __syncwarp();

    // ---- silu(D1 + b1) -> H bf16 hi/lo (own warp's rows) ----
    {
        const int j0  = (tid & 31) * 4;
        const int ebl = (tid >> 5) * 16;
        float4 bb = *(const float4*)&b1[j0];
        #pragma unroll 4
        for (int e = 0; e < 16; e++) {
            int ei = ebl + e;
            float4 d = *(float4*)&sScr[scr_w(ei, j0)];
            float x0 = d.x + bb.x, x1 = d.y + bb.y, x2 = d.z + bb.z, x3 = d.w + bb.w;
            float s0 = x0 / (1.0f + __expf(-x0));
            float s1 = x1 / (1.0f + __expf(-x1));
            float s2 = x2 / (1.0f + __expf(-x2));
            float s3 = x3 / (1.0f + __expf(-x3));
            u32 hA, lA, hB, lB;
            split2(s0, s1, hA, lA); split2(s2, s3, hB, lB);
            int off = toff(ei, j0 >> 3) + (j0 & 7) * 2;
            *(uint2*)(smem + OFF_AHI + off) = make_uint2(hA, hB);
            *(uint2*)(smem + OFF_ALO + off) = make_uint2(lA, lB);
        }
    }
    cpa_wait0();
    __syncthreads();   // H + W2[0] ready

    // ---- GEMM2 chunk 0 ----
    #pragma unroll
    for (int q = 0; q < 16; q++)
        acc[q][0] = acc[q][1] = acc[q][2] = acc[q][3] = 0.0f;
    gemm_tile(sb + OFF_AHI, sb + OFF_ALO, sb + OFF_WHI, sb + OFF_WLO, m0, lane, acc);
    __syncthreads();
    copyW_async(sb, g_W2hi + 32768, g_W2lo + 32768, tid);
    dump_all(sScr, acc, m0, lane);
    __syncwarp();
    epilogue<0>(sScr, sRbfT, sUnit, sEnv, sBin, v_i, Wr_g, b2, br,
                e0, nvalid, tid, st0);
    cpa_wait0();
    __syncthreads();

    // ---- GEMM2 chunk 1 ----
    #pragma unroll
    for (int q = 0; q < 16; q++)
        acc[q][0] = acc[q][1] = acc[q][2] = acc[q][3] = 0.0f;
    gemm_tile(sb + OFF_AHI, sb + OFF_ALO, sb + OFF_WHI, sb + OFF_WLO, m0, lane, acc);
    __syncthreads();
    copyW_async(sb, g_W2hi + 65536, g_W2lo + 65536, tid);
    dump_all(sScr, acc, m0, lane);
    __syncwarp();
    epilogue<1>(sScr, sRbfT, sUnit, sEnv, sBin, v_i, Wr_g, b2, br,
                e0, nvalid, tid, st0);
    cpa_wait0();
    __syncthreads();

    // ---- GEMM2 chunk 2 ----
    #pragma unroll
    for (int q = 0; q < 16; q++)
        acc[q][0] = acc[q][1] = acc[q][2] = acc[q][3] = 0.0f;
    gemm_tile(sb + OFF_AHI, sb + OFF_ALO, sb + OFF_WHI, sb + OFF_WLO, m0, lane, acc);
    dump_all(sScr, acc, m0, lane);
    __syncwarp();
    epilogue<2>(sScr, sRbfT, sUnit, sEnv, sBin, v_i, Wr_g, b2, br,
                e0, nvalid, tid, st0);
}

__global__ void cmb_final(float* __restrict__ out) {
    int bin = blockIdx.x;
    int f   = threadIdx.x;
    float ic = 1.0f / fmaxf(g_cnt[bin], 1.0f);
    out[bin * FEAT + f] = g_acc_s[bin * FEAT + f] * ic;
    #pragma unroll
    for (int x = 0; x < 3; x++)
        out[NB * FEAT + bin * 384 + f * 3 + x] =
            g_acc_v[bin * 3 * FEAT + x * FEAT + f] * ic;
}

extern "C" void kernel_launch(void* const* d_in, const int* in_sizes, int n_in,
                              void* d_out, int out_size)
{
    const float* s_i     = (const float*)d_in[0];
    const float* v_i     = (const float*)d_in[1];
    const float* r_iI    = (const float*)d_in[2];
    const float* W1      = (const float*)d_in[3];
    const float* b1      = (const float*)d_in[4];
    const float* W2      = (const float*)d_in[5];
    const float* b2      = (const float*)d_in[6];
    const float* Wr      = (const float*)d_in[7];
    const float* br      = (const float*)d_in[8];
    const int*   mapping = (const int*)d_in[9];
    float* out = (float*)d_out;
    (void)in_sizes; (void)n_in; (void)out_size;

    cudaFuncSetAttribute((const void*)cmb_main,
                         cudaFuncAttributeMaxDynamicSharedMemorySize, SMEM_BYTES);

    cmb_prep<<<256, 256>>>(W1, W2);
    cmb_zero<<<(NB * 3 * FEAT + 255) / 256, 256>>>();
    cmb_main<<<NBLK, 256, SMEM_BYTES>>>(s_i, v_i, r_iI, b1, b2, Wr, br, mapping);
    cmb_final<<<NB, FEAT>>>(out);
}

// round 7
// speedup vs baseline: 2.2827x; 1.1450x over previous
#include <cuda_runtime.h>
#include <cuda_fp16.h>
#include <math.h>

// ContractiveMessageBlock — Round 6: fp16 2-pass HMMA GEMMs (A split hi/lo fp16,
// B single fp16). Rest of R5 structure unchanged (SCR epilogue, red.v4 scatter,
// cp.async W prefetch, register split0).

#define E_TOT   200000
#define FEAT    128
#define TM      128
#define NBLK    ((E_TOT + TM - 1) / TM)   // 1563
#define NB      2000
#define NRBF    20
#define PI_OVER_CUT 0.62831853071795864769f

typedef unsigned long long u64;
typedef unsigned int u32;

// ---------------- f32x2 / misc helpers ----------------
__device__ __forceinline__ u64 fma2(u64 a, u64 b, u64 c) {
    u64 d; asm("fma.rn.f32x2 %0, %1, %2, %3;" : "=l"(d) : "l"(a), "l"(b), "l"(c)); return d;
}
__device__ __forceinline__ u64 mul2(u64 a, u64 b) {
    u64 d; asm("mul.rn.f32x2 %0, %1, %2;" : "=l"(d) : "l"(a), "l"(b)); return d;
}
__device__ __forceinline__ u64 add2(u64 a, u64 b) {
    u64 d; asm("add.rn.f32x2 %0, %1, %2;" : "=l"(d) : "l"(a), "l"(b)); return d;
}
__device__ __forceinline__ u64 dup2(float x) {
    u64 d; asm("mov.b64 %0, {%1, %1};" : "=l"(d) : "f"(x)); return d;
}
__device__ __forceinline__ u64 pk2(float a, float b) {
    u64 d; asm("mov.b64 %0, {%1, %2};" : "=l"(d) : "f"(a), "f"(b)); return d;
}
__device__ __forceinline__ void unpack2(u64 a, float& lo, float& hi) {
    asm("mov.b64 {%0, %1}, %2;" : "=f"(lo), "=f"(hi) : "l"(a));
}
__device__ __forceinline__ void red_add_v4(float* p, float a, float b, float c, float d) {
    asm volatile("red.global.add.v4.f32 [%0], {%1, %2, %3, %4};"
                 :: "l"(p), "f"(a), "f"(b), "f"(c), "f"(d) : "memory");
}
__device__ __forceinline__ u32 smem_u32(const void* p) {
    u32 a; asm("{ .reg .u64 t; cvta.to.shared.u64 t, %1; cvt.u32.u64 %0, t; }"
               : "=r"(a) : "l"(p));
    return a;
}
// fp16 split of an f32 pair: hi = h2(x,y), lo = h2(residual)
__device__ __forceinline__ void split2h(float x, float y, u32& hi, u32& lo) {
    __half2 h = __floats2half2_rn(x, y);
    float rx = x - __half2float(__low2half(h));
    float ry = y - __half2float(__high2half(h));
    __half2 l = __floats2half2_rn(rx, ry);
    hi = *(u32*)&h; lo = *(u32*)&l;
}
__device__ __forceinline__ void cpa16(u32 s, const void* g) {
    asm volatile("cp.async.cg.shared.global [%0], [%1], 16;" :: "r"(s), "l"(g));
}
__device__ __forceinline__ void cpa_commit() {
    asm volatile("cp.async.commit_group;" ::: "memory");
}
__device__ __forceinline__ void cpa_wait0() {
    asm volatile("cp.async.wait_group 0;" ::: "memory");
}

// ---------------- mma / ldmatrix ----------------
__device__ __forceinline__ void ldsm4(u32* r, u32 addr) {
    asm volatile("ldmatrix.sync.aligned.m8n8.x4.shared.b16 {%0,%1,%2,%3}, [%4];"
                 : "=r"(r[0]), "=r"(r[1]), "=r"(r[2]), "=r"(r[3]) : "r"(addr));
}
__device__ __forceinline__ void mma16816(float* d, const u32* a, u32 b0, u32 b1) {
    asm volatile(
        "mma.sync.aligned.m16n8k16.row.col.f32.f16.f16.f32 "
        "{%0,%1,%2,%3}, {%4,%5,%6,%7}, {%8,%9}, {%0,%1,%2,%3};"
        : "+f"(d[0]), "+f"(d[1]), "+f"(d[2]), "+f"(d[3])
        : "r"(a[0]), "r"(a[1]), "r"(a[2]), "r"(a[3]), "r"(b0), "r"(b1));
}

// fp16 tile [128 rows][128 k]: 16B granules, XOR swizzle.
__device__ __host__ __forceinline__ int toff(int row, int kg) {
    return row * 256 + (((kg ^ (row & 7)) & 15) << 4);
}
// fp32 scratch [128 e][128 c], word index with 4-word-granule XOR swizzle.
__device__ __forceinline__ int scr_w(int e, int c) {
    return e * 128 + (((((c >> 2)) ^ (e & 7)) & 31) << 2) + (c & 3);
}

// ---------------- global scratch ----------------
__device__ __align__(16) float g_acc_s[NB * FEAT];      // [bin][f]
__device__ __align__(16) float g_acc_v[NB * 3 * FEAT];  // [bin][x][f]
__device__ float g_cnt[NB];
__device__ __align__(16) unsigned char g_W1[32768];          // fp16 tile
__device__ __align__(16) unsigned char g_W2[3 * 32768];      // fp16 tiles

// ---------------- smem offsets (bytes) ----------------
#define OFF_AHI  0        // 32768  A then H, fp16 hi
#define OFF_ALO  32768    // 32768  A then H, fp16 lo (split residual)
#define OFF_W    65536    // 32768  current W tile (fp16)
#define OFF_SCR  98304    // 65536  fp32 D dump [128][128]
#define OFF_RBF  163840   // 10240  rbf [20][128]
#define OFF_UNIT 174080   // 1536   unit [3][128]
#define OFF_ENV  175616   // 512
#define OFF_BIN  176128   // 512 (int)
#define SMEM_BYTES 176640

__global__ void cmb_zero() {
    int i = blockIdx.x * 256 + threadIdx.x;
    if (i < NB * FEAT)     g_acc_s[i] = 0.0f;
    if (i < NB * 3 * FEAT) g_acc_v[i] = 0.0f;
    if (i < NB)            g_cnt[i]   = 0.0f;
}

// W1/W2 -> single fp16 tiles in swizzled [n][k] layout (B operand, TN gemm).
__global__ void cmb_prep(const float* __restrict__ W1, const float* __restrict__ W2) {
    int i = blockIdx.x * 256 + threadIdx.x;     // 0..65535
    if (i < 16384) {
        int n = i & 127, k = i >> 7;
        float v = W1[k * 128 + n];
        int off = toff(n, k >> 3) + (k & 7) * 2;
        *(__half*)(g_W1 + off) = __float2half_rn(v);
    } else if (i < 65536) {
        int r = i - 16384;
        int c = r >> 14;
        int t = r & 16383;
        int n = t & 127, k = t >> 7;
        float v = W2[k * 384 + c * 128 + n];
        int off = c * 32768 + toff(n, k >> 3) + (k & 7) * 2;
        *(__half*)(g_W2 + off) = __float2half_rn(v);
    }
}

// Issue cp.async for one W tile (32KB).
__device__ __forceinline__ void copyW_async(u32 sb, const unsigned char* g, int tid) {
    u32 d = sb + OFF_W;
    #pragma unroll
    for (int t = 0; t < 8; t++) {
        int i = tid + t * 256;
        cpa16(d + i * 16, g + i * 16);
    }
    cpa_commit();
}

// 2-pass fp16 split GEMM: acc += (Ahi + Alo) * B over warp stripe.
__device__ __forceinline__ void gemm_tile(u32 aHi, u32 aLo, u32 bW,
                                          int m0, int lane, float acc[16][4]) {
    const int r  = lane & 7;
    const int hf = (lane >> 3) & 1;
    const int kq = lane >> 4;
    const int arow = m0 + hf * 8 + r;
    #pragma unroll 2
    for (int ks = 0; ks < 8; ks++) {
        int kg = ks * 2 + kq;
        u32 ah[4], al[4];
        u32 aoff = (u32)toff(arow, kg);
        ldsm4(ah, aHi + aoff);
        ldsm4(al, aLo + aoff);
        #pragma unroll
        for (int ng = 0; ng < 8; ng++) {
            u32 b[4];
            u32 boff = (u32)toff(ng * 16 + hf * 8 + r, kg);
            ldsm4(b, bW + boff);
            mma16816(acc[2 * ng],     ah, b[0], b[2]);
            mma16816(acc[2 * ng + 1], ah, b[1], b[3]);
            mma16816(acc[2 * ng],     al, b[0], b[2]);
            mma16816(acc[2 * ng + 1], al, b[1], b[3]);
        }
    }
}

__device__ __forceinline__ void dump_all(float* scr, const float acc[16][4],
                                         int m0, int lane) {
    const int r0 = m0 + (lane >> 2);
    const int cb = (lane & 3) * 2;
    #pragma unroll
    for (int ng = 0; ng < 8; ng++)
        #pragma unroll
        for (int s = 0; s < 2; s++) {
            int c = ng * 16 + s * 8 + cb;
            const float* a = acc[2 * ng + s];
            *(float2*)&scr[scr_w(r0, c)]     = make_float2(a[0], a[1]);
            *(float2*)&scr[scr_w(r0 + 8, c)] = make_float2(a[2], a[3]);
        }
}

// Fused epilogue for chunk C. Fully unrolled over 16 edges so st0 stays in regs.
template <int C>
__device__ __forceinline__ void epilogue(
    const float* sScr, const float* sRbfT, const float* sUnit,
    const float* sEnv, const int* sBin,
    const float* __restrict__ v_i, const float* __restrict__ Wr_g,
    const float* __restrict__ b2, const float* __restrict__ br,
    long e0, int nvalid, int tid, float st0[16][4])
{
    const int j0  = (tid & 31) * 4;
    const int ebl = (tid >> 5) * 16;
    u64 wra[NRBF], wrb[NRBF];
    #pragma unroll
    for (int n = 0; n < NRBF; n++) {
        float4 w = *(const float4*)&Wr_g[n * 384 + C * 128 + j0];
        wra[n] = pk2(w.x, w.y); wrb[n] = pk2(w.z, w.w);
    }
    float4 b2v = *(const float4*)&b2[C * 128 + j0];
    float4 brv = *(const float4*)&br[C * 128 + j0];
    u64 b2a = pk2(b2v.x, b2v.y), b2b = pk2(b2v.z, b2v.w);
    u64 bra = pk2(brv.x, brv.y), brb = pk2(brv.z, brv.w);

    #pragma unroll
    for (int e = 0; e < 16; e++) {
        int ei = ebl + e;
        u64 w0 = bra, w1 = brb;
        #pragma unroll
        for (int n = 0; n < NRBF; n++) {
            u64 f = dup2(sRbfT[n * 128 + ei]);
            w0 = fma2(f, wra[n], w0);
            w1 = fma2(f, wrb[n], w1);
        }
        float4 d = *(const float4*)&sScr[scr_w(ei, j0)];
        u64 envd = dup2(sEnv[ei]);
        u64 i01 = mul2(add2(pk2(d.x, d.y), b2a), mul2(w0, envd));
        u64 i23 = mul2(add2(pk2(d.z, d.w), b2b), mul2(w1, envd));
        float i0, i1, i2, i3;
        unpack2(i01, i0, i1); unpack2(i23, i2, i3);

        if (C == 0) {
            st0[e][0] = i0; st0[e][1] = i1; st0[e][2] = i2; st0[e][3] = i3;
        } else if (C == 1) {
            if (ei < nvalid) {
                int bin = sBin[ei];
                red_add_v4(&g_acc_s[bin * FEAT + j0], i0, i1, i2, i3);
            }
        } else {
            if (ei < nvalid) {
                int bin = sBin[ei];
                const float4* vg =
                    (const float4*)(v_i + ((size_t)(e0 + ei) * FEAT + j0) * 3);
                float4 va = vg[0], vb = vg[1], vc2 = vg[2];
                float vf[12] = { va.x, va.y, va.z, va.w,
                                 vb.x, vb.y, vb.z, vb.w,
                                 vc2.x, vc2.y, vc2.z, vc2.w };
                float uu[3] = { sUnit[ei], sUnit[128 + ei], sUnit[256 + ei] };
                #pragma unroll
                for (int x = 0; x < 3; x++)
                    red_add_v4(&g_acc_v[bin * 3 * FEAT + x * FEAT + j0],
                        fmaf(i0, uu[x], st0[e][0] * vf[0 + x]),
                        fmaf(i1, uu[x], st0[e][1] * vf[3 + x]),
                        fmaf(i2, uu[x], st0[e][2] * vf[6 + x]),
                        fmaf(i3, uu[x], st0[e][3] * vf[9 + x]));
            }
        }
    }
}

__global__ void __launch_bounds__(256, 1)
cmb_main(const float* __restrict__ s_i, const float* __restrict__ v_i,
         const float* __restrict__ r_iI, const float* __restrict__ b1,
         const float* __restrict__ b2, const float* __restrict__ Wr_g,
         const float* __restrict__ br, const int* __restrict__ mapping)
{
    extern __shared__ char smem[];
    const u32 sb = smem_u32(smem);
    float* sScr  = (float*)(smem + OFF_SCR);
    float* sRbfT = (float*)(smem + OFF_RBF);
    float* sUnit = (float*)(smem + OFF_UNIT);
    float* sEnv  = (float*)(smem + OFF_ENV);
    int*   sBin  = (int*)(smem + OFF_BIN);

    const int tid  = threadIdx.x;
    const int lane = tid & 31;
    const int m0   = (tid >> 5) * 16;
    const long e0  = (long)blockIdx.x * TM;
    const int nvalid = (int)min((long)TM, (long)E_TOT - e0);

    // ---- W1 prefetch (cp.async) ----
    copyW_async(sb, g_W1, tid);

    // ---- A tile: s_i -> fp16 hi/lo (split) swizzled ----
    for (int i = tid; i < 2048; i += 256) {
        int row = i >> 4, kg = i & 15;
        float4 va, vb;
        if (row < nvalid) {
            const float4* g = (const float4*)(s_i + ((size_t)(e0 + row)) * FEAT + kg * 8);
            va = g[0]; vb = g[1];
        } else {
            va = make_float4(0.f, 0.f, 0.f, 0.f); vb = va;
        }
        u32 h0, l0, h1, l1, h2, l2, h3, l3;
        split2h(va.x, va.y, h0, l0); split2h(va.z, va.w, h1, l1);
        split2h(vb.x, vb.y, h2, l2); split2h(vb.z, vb.w, h3, l3);
        int off = toff(row, kg);
        *(uint4*)(smem + OFF_AHI + off) = make_uint4(h0, h1, h2, h3);
        *(uint4*)(smem + OFF_ALO + off) = make_uint4(l0, l1, l2, l3);
    }
    // ---- per-edge preprocess ----
    if (tid < TM) {
        int e = tid;
        if (e < nvalid) {
            long eg = e0 + e;
            float r0 = r_iI[eg * 3 + 0], r1 = r_iI[eg * 3 + 1], r2 = r_iI[eg * 3 + 2];
            float d = sqrtf(r0 * r0 + r1 * r1 + r2 * r2 + 3e-8f);
            float id = 1.0f / d;
            sUnit[0 * 128 + e] = r0 * id;
            sUnit[1 * 128 + e] = r1 * id;
            sUnit[2 * 128 + e] = r2 * id;
            sEnv[e] = (d < 5.0f) ? 0.5f * (cosf(PI_OVER_CUT * d) + 1.0f) : 0.0f;
            float ang = PI_OVER_CUT * d;
            #pragma unroll
            for (int n = 0; n < NRBF; n++)
                sRbfT[n * 128 + e] = sinf((float)(n + 1) * ang) * id;
            int b = mapping[eg];
            sBin[e] = b;
            atomicAdd(&g_cnt[b], 1.0f);
        } else {
            sUnit[e] = sUnit[128 + e] = sUnit[256 + e] = 0.0f;
            sEnv[e] = 0.0f; sBin[e] = 0;
            #pragma unroll
            for (int n = 0; n < NRBF; n++) sRbfT[n * 128 + e] = 0.0f;
        }
    }
    cpa_wait0();
    __syncthreads();

    float acc[16][4];
    float st0[16][4];

    // ---- GEMM1 ----
    #pragma unroll
    for (int q = 0; q < 16; q++)
        acc[q][0] = acc[q][1] = acc[q][2] = acc[q][3] = 0.0f;
    gemm_tile(sb + OFF_AHI, sb + OFF_ALO, sb + OFF_W, m0, lane, acc);
    __syncthreads();                  // all warps done reading W1
    copyW_async(sb, g_W2, tid);       // prefetch W2[0] under dump+silu
    dump_all(sScr, acc, m0, lane);
    __syncwarp();

    // ---- silu(D1 + b1) -> H fp16 hi/lo (own warp's rows) ----
    {
        const int j0  = (tid & 31) * 4;
        const int ebl = (tid >> 5) * 16;
        float4 bb = *(const float4*)&b1[j0];
        #pragma unroll 4
        for (int e = 0; e < 16; e++) {
            int ei = ebl + e;
            float4 d = *(float4*)&sScr[scr_w(ei, j0)];
            float x0 = d.x + bb.x, x1 = d.y + bb.y, x2 = d.z + bb.z, x3 = d.w + bb.w;
            float s0 = x0 / (1.0f + __expf(-x0));
            float s1 = x1 / (1.0f + __expf(-x1));
            float s2 = x2 / (1.0f + __expf(-x2));
            float s3 = x3 / (1.0f + __expf(-x3));
            u32 hA, lA, hB, lB;
            split2h(s0, s1, hA, lA); split2h(s2, s3, hB, lB);
            int off = toff(ei, j0 >> 3) + (j0 & 7) * 2;
            *(uint2*)(smem + OFF_AHI + off) = make_uint2(hA, hB);
            *(uint2*)(smem + OFF_ALO + off) = make_uint2(lA, lB);
        }
    }
    cpa_wait0();
    __syncthreads();   // H + W2[0] ready

    // ---- GEMM2 chunk 0 ----
    #pragma unroll
    for (int q = 0; q < 16; q++)
        acc[q][0] = acc[q][1] = acc[q][2] = acc[q][3] = 0.0f;
    gemm_tile(sb + OFF_AHI, sb + OFF_ALO, sb + OFF_W, m0, lane, acc);
    __syncthreads();
    copyW_async(sb, g_W2 + 32768, tid);
    dump_all(sScr, acc, m0, lane);
    __syncwarp();
    epilogue<0>(sScr, sRbfT, sUnit, sEnv, sBin, v_i, Wr_g, b2, br,
                e0, nvalid, tid, st0);
    cpa_wait0();
    __syncthreads();

    // ---- GEMM2 chunk 1 ----
    #pragma unroll
    for (int q = 0; q < 16; q++)
        acc[q][0] = acc[q][1] = acc[q][2] = acc[q][3] = 0.0f;
    gemm_tile(sb + OFF_AHI, sb + OFF_ALO, sb + OFF_W, m0, lane, acc);
    __syncthreads();
    copyW_async(sb, g_W2 + 65536, tid);
    dump_all(sScr, acc, m0, lane);
    __syncwarp();
    epilogue<1>(sScr, sRbfT, sUnit, sEnv, sBin, v_i, Wr_g, b2, br,
                e0, nvalid, tid, st0);
    cpa_wait0();
    __syncthreads();

    // ---- GEMM2 chunk 2 ----
    #pragma unroll
    for (int q = 0; q < 16; q++)
        acc[q][0] = acc[q][1] = acc[q][2] = acc[q][3] = 0.0f;
    gemm_tile(sb + OFF_AHI, sb + OFF_ALO, sb + OFF_W, m0, lane, acc);
    dump_all(sScr, acc, m0, lane);
    __syncwarp();
    epilogue<2>(sScr, sRbfT, sUnit, sEnv, sBin, v_i, Wr_g, b2, br,
                e0, nvalid, tid, st0);
}

__global__ void cmb_final(float* __restrict__ out) {
    int bin = blockIdx.x;
    int f   = threadIdx.x;
    float ic = 1.0f / fmaxf(g_cnt[bin], 1.0f);
    out[bin * FEAT + f] = g_acc_s[bin * FEAT + f] * ic;
    #pragma unroll
    for (int x = 0; x < 3; x++)
        out[NB * FEAT + bin * 384 + f * 3 + x] =
            g_acc_v[bin * 3 * FEAT + x * FEAT + f] * ic;
}

extern "C" void kernel_launch(void* const* d_in, const int* in_sizes, int n_in,
                              void* d_out, int out_size)
{
    const float* s_i     = (const float*)d_in[0];
    const float* v_i     = (const float*)d_in[1];
    const float* r_iI    = (const float*)d_in[2];
    const float* W1      = (const float*)d_in[3];
    const float* b1      = (const float*)d_in[4];
    const float* W2      = (const float*)d_in[5];
    const float* b2      = (const float*)d_in[6];
    const float* Wr      = (const float*)d_in[7];
    const float* br      = (const float*)d_in[8];
    const int*   mapping = (const int*)d_in[9];
    float* out = (float*)d_out;
    (void)in_sizes; (void)n_in; (void)out_size;

    cudaFuncSetAttribute((const void*)cmb_main,
                         cudaFuncAttributeMaxDynamicSharedMemorySize, SMEM_BYTES);

    cmb_prep<<<256, 256>>>(W1, W2);
    cmb_zero<<<(NB * 3 * FEAT + 255) / 256, 256>>>();
    cmb_main<<<NBLK, 256, SMEM_BYTES>>>(s_i, v_i, r_iI, b1, b2, Wr, br, mapping);
    cmb_final<<<NB, FEAT>>>(out);
}